// round 16
// baseline (speedup 1.0000x reference)
#include <cuda_runtime.h>
#include <cuda_fp16.h>
#include <cstdint>
#include <math.h>

#define Bb     8
#define NN     4096
#define RR     32768
#define DD     256
#define D2     512
#define HEADS  8
#define DK     32
#define EPS    1e-5f

// ---------------- scratch (device globals; no runtime allocation) -----------
__device__ __align__(16) __half g_x1h [RR * D2];
__device__ __align__(16) __half g_n1h [RR * DD];
__device__ __align__(16) __half g_E   [RR * DD];
__device__ __align__(16) __half g_Y   [RR * DD];
__device__ __align__(16) __half g_w1h [DD * D2];
__device__ __align__(16) __half g_b2h [Bb * D2 * DD];
__device__ __align__(16) float  g_Spart[4 * Bb * HEADS * DK * DK];

// ---------------- helpers ----------------------------------------------------
__device__ __forceinline__ uint32_t s2u(const void* p) {
    uint32_t a;
    asm("{ .reg .u64 t; cvta.to.shared.u64 t, %1; cvt.u32.u64 %0, t; }"
        : "=r"(a) : "l"(p));
    return a;
}
__device__ __forceinline__ void cvt8(const float4& a, const float4& b, uint4& o) {
    __half2 h0 = __floats2half2_rn(a.x, a.y);
    __half2 h1 = __floats2half2_rn(a.z, a.w);
    __half2 h2 = __floats2half2_rn(b.x, b.y);
    __half2 h3 = __floats2half2_rn(b.z, b.w);
    o.x = *reinterpret_cast<uint32_t*>(&h0);
    o.y = *reinterpret_cast<uint32_t*>(&h1);
    o.z = *reinterpret_cast<uint32_t*>(&h2);
    o.w = *reinterpret_cast<uint32_t*>(&h3);
}
__device__ __forceinline__ void ldsm4(uint32_t* r, uint32_t addr) {
    asm volatile("ldmatrix.sync.aligned.m8n8.x4.shared.b16 {%0,%1,%2,%3}, [%4];"
                 : "=r"(r[0]), "=r"(r[1]), "=r"(r[2]), "=r"(r[3]) : "r"(addr));
}
__device__ __forceinline__ void ldsm4t(uint32_t* r, uint32_t addr) {
    asm volatile("ldmatrix.sync.aligned.m8n8.x4.trans.shared.b16 {%0,%1,%2,%3}, [%4];"
                 : "=r"(r[0]), "=r"(r[1]), "=r"(r[2]), "=r"(r[3]) : "r"(addr));
}
__device__ __forceinline__ void mma16816(float* c, const uint32_t* a,
                                         const uint32_t* b) {
    asm volatile(
        "mma.sync.aligned.m16n8k16.row.col.f32.f16.f16.f32 "
        "{%0,%1,%2,%3}, {%4,%5,%6,%7}, {%8,%9}, {%0,%1,%2,%3};"
        : "+f"(c[0]), "+f"(c[1]), "+f"(c[2]), "+f"(c[3])
        : "r"(a[0]), "r"(a[1]), "r"(a[2]), "r"(a[3]), "r"(b[0]), "r"(b[1]));
}
__device__ __forceinline__ void cpa16(uint32_t dst, const void* src) {
    asm volatile("cp.async.ca.shared.global [%0], [%1], 16;" :: "r"(dst), "l"(src));
}
#define CP_COMMIT() asm volatile("cp.async.commit_group;")
#define CP_WAIT0()  asm volatile("cp.async.wait_group 0;")
#define CP_WAIT1()  asm volatile("cp.async.wait_group 1;")

__device__ __forceinline__ uint32_t sw_off(int row, int cch) {
    return (uint32_t)(row * 64 + ((cch ^ ((row >> 1) & 3)) << 4));
}

// ============ prep: x1->fp16 AND LN(x2)+exp+softmax (2 rows/warp) ============
__global__ __launch_bounds__(256) void prep_k(
    const float* __restrict__ x1, const float* __restrict__ x2,
    const float* __restrict__ g, const float* __restrict__ b,
    __half* __restrict__ x1h, __half* __restrict__ Eg, __half* __restrict__ Yg)
{
    const int w    = threadIdx.x >> 5;
    const int lane = threadIdx.x & 31;
    const int r0   = blockIdx.x * 16 + w * 2;
    const int ci   = lane * 8;

    // ---- convert x1 rows r0, r0+1 (16 floats per lane per row) ----
#pragma unroll
    for (int rr = 0; rr < 2; rr++) {
        const float* xp = x1 + (size_t)(r0 + rr) * D2 + lane * 16;
        float4 a0 = *(const float4*)xp;
        float4 a1 = *(const float4*)(xp + 4);
        float4 a2 = *(const float4*)(xp + 8);
        float4 a3 = *(const float4*)(xp + 12);
        uint4 v0, v1;
        cvt8(a0, a1, v0);
        cvt8(a2, a3, v1);
        __half* dp = x1h + (size_t)(r0 + rr) * D2 + lane * 16;
        *(uint4*)dp       = v0;
        *(uint4*)(dp + 8) = v1;
    }

    // ---- LN(x2)+exp+channel-softmax for rows r0, r0+1 ----
    float4 A[2], C[2];
#pragma unroll
    for (int rr = 0; rr < 2; rr++) {
        const float* p = x2 + (size_t)(r0 + rr) * DD + ci;
        A[rr] = *(const float4*)p;
        C[rr] = *(const float4*)(p + 4);
    }

    float4 g0 = *(const float4*)(g + ci);
    float4 g1 = *(const float4*)(g + ci + 4);
    float4 b0 = *(const float4*)(b + ci);
    float4 b1 = *(const float4*)(b + ci + 4);

    float sm[2], rs[2];
#pragma unroll
    for (int rr = 0; rr < 2; rr++) {
        float s = A[rr].x + A[rr].y + A[rr].z + A[rr].w
                + C[rr].x + C[rr].y + C[rr].z + C[rr].w;
#pragma unroll
        for (int o = 16; o; o >>= 1) s += __shfl_xor_sync(0xffffffffu, s, o);
        sm[rr] = s * (1.0f / DD);
    }
#pragma unroll
    for (int rr = 0; rr < 2; rr++) {
        A[rr].x -= sm[rr]; A[rr].y -= sm[rr]; A[rr].z -= sm[rr]; A[rr].w -= sm[rr];
        C[rr].x -= sm[rr]; C[rr].y -= sm[rr]; C[rr].z -= sm[rr]; C[rr].w -= sm[rr];
        float s2 = A[rr].x*A[rr].x + A[rr].y*A[rr].y + A[rr].z*A[rr].z + A[rr].w*A[rr].w
                 + C[rr].x*C[rr].x + C[rr].y*C[rr].y + C[rr].z*C[rr].z + C[rr].w*C[rr].w;
#pragma unroll
        for (int o = 16; o; o >>= 1) s2 += __shfl_xor_sync(0xffffffffu, s2, o);
        rs[rr] = rsqrtf(s2 * (1.0f / DD) + EPS);
    }

#pragma unroll
    for (int rr = 0; rr < 2; rr++) {
        float4 e0, e1;
        e0.x = __expf(A[rr].x*rs[rr]*g0.x + b0.x);
        e0.y = __expf(A[rr].y*rs[rr]*g0.y + b0.y);
        e0.z = __expf(A[rr].z*rs[rr]*g0.z + b0.z);
        e0.w = __expf(A[rr].w*rs[rr]*g0.w + b0.w);
        e1.x = __expf(C[rr].x*rs[rr]*g1.x + b1.x);
        e1.y = __expf(C[rr].y*rs[rr]*g1.y + b1.y);
        e1.z = __expf(C[rr].z*rs[rr]*g1.z + b1.z);
        e1.w = __expf(C[rr].w*rs[rr]*g1.w + b1.w);

        float qs = e0.x + e0.y + e0.z + e0.w + e1.x + e1.y + e1.z + e1.w;
        qs += __shfl_xor_sync(0xffffffffu, qs, 1);
        qs += __shfl_xor_sync(0xffffffffu, qs, 2);
        const float inv = 1.0f / qs;

        float4 y0, y1;
        y0.x = e0.x * inv; y0.y = e0.y * inv; y0.z = e0.z * inv; y0.w = e0.w * inv;
        y1.x = e1.x * inv; y1.y = e1.y * inv; y1.z = e1.z * inv; y1.w = e1.w * inv;

        uint4 ev, yv;
        cvt8(e0, e1, ev);
        cvt8(y0, y1, yv);
        *(uint4*)(Eg + (size_t)(r0 + rr) * DD + ci) = ev;
        *(uint4*)(Yg + (size_t)(r0 + rr) * DD + ci) = yv;
    }
}

// ============ GEMM1 fused: n1h = fp16( LN(x1h @ W1 + b1) ) ===================
// fp16 A via cp.async; 3 buffers, distance 2 (proven-safe ring).
#define G1_A_ST  8192
#define G1_B_ST  16384
#define G1_B_OFF (3 * G1_A_ST)
#define G1_VEC   (G1_B_OFF + 3 * G1_B_ST)
#define G1_RED   (G1_VEC + 3 * 256 * 4)
#define G1_SMEM  (G1_RED + 2 * 128 * 4)

__global__ __launch_bounds__(512, 1) void gemm1_ln_k(
    const __half* __restrict__ x1h, const __half* __restrict__ w1,
    const float* __restrict__ bias, const float* __restrict__ g,
    const float* __restrict__ bvec, __half* __restrict__ n1h)
{
    extern __shared__ char smem[];
    const uint32_t uA = s2u(smem);
    const uint32_t uB = uA + G1_B_OFF;
    float* sBias = (float*)(smem + G1_VEC);
    float* sG    = sBias + 256;
    float* sBv   = sG + 256;
    float* rsum  = (float*)(smem + G1_RED);
    float* rsq   = rsum + 128;

    const int t = threadIdx.x, lane = t & 31, wid = t >> 5;
    const int wm = (wid & 3) * 32;
    const int wn = (wid >> 2) * 64;
    const int row0 = blockIdx.x * 128;

    if (t < 256) { sBias[t] = bias[t]; sG[t] = g[t]; sBv[t] = bvec[t]; }
    if (t < 128) { rsum[t] = 0.f; rsq[t] = 0.f; }

    const int ar = t >> 2, aq = t & 3;
    const __half* aptr = x1h + (size_t)(row0 + ar) * D2 + aq * 8;
    const uint32_t staA = sw_off(ar, aq);

    float acc[2][8][4];
#pragma unroll
    for (int i = 0; i < 2; i++)
#pragma unroll
        for (int j = 0; j < 8; j++)
#pragma unroll
            for (int k = 0; k < 4; k++) acc[i][j][k] = 0.f;

    const int ti = lane >> 3, tr = lane & 7;
    const int a_dm = (ti & 1) * 8, a_dkc = ti >> 1;
    const int b_dn = (ti >> 1) * 8, b_dkc = ti & 1;

    auto stage = [&](int s, int kk) {
        const int k0 = kk * 32;
        cpa16(uA + s * G1_A_ST + staA, aptr + k0);
#pragma unroll
        for (int j = 0; j < 2; j++) {
            const int idx = t + j * 512;
            const int br = idx >> 2, bq = idx & 3;
            cpa16(uB + s * G1_B_ST + sw_off(br, bq),
                  w1 + (size_t)br * D2 + k0 + bq * 8);
        }
        CP_COMMIT();
    };

    stage(0, 0);
    stage(1, 1);

    const int nk = D2 / 32;   // 16
    for (int kk = 0; kk < nk; kk++) {
        if (kk + 1 < nk) CP_WAIT1(); else CP_WAIT0();
        __syncthreads();
        if (kk + 2 < nk) stage((kk + 2) % 3, kk + 2);
        const int buf = kk % 3;
        const uint32_t bA = uA + buf * G1_A_ST, bB = uB + buf * G1_B_ST;
#pragma unroll
        for (int ks = 0; ks < 2; ks++) {
            uint32_t af[2][4], bf[4][4];
#pragma unroll
            for (int mf = 0; mf < 2; mf++)
                ldsm4(af[mf], bA + sw_off(wm + mf * 16 + a_dm + tr, ks * 2 + a_dkc));
#pragma unroll
            for (int g2 = 0; g2 < 4; g2++)
                ldsm4(bf[g2], bB + sw_off(wn + g2 * 16 + b_dn + tr, ks * 2 + b_dkc));
#pragma unroll
            for (int mf = 0; mf < 2; mf++)
#pragma unroll
                for (int nf = 0; nf < 8; nf++)
                    mma16816(acc[mf][nf], af[mf], &bf[nf >> 1][(nf & 1) * 2]);
        }
    }

    // ---- epilogue: bias + LN over 256 cols, write fp16 ----
    const int rl = lane >> 2, cl = (lane & 3) * 2;
#pragma unroll
    for (int mf = 0; mf < 2; mf++) {
        float s0 = 0.f, q0 = 0.f, s1 = 0.f, q1 = 0.f;
#pragma unroll
        for (int nf = 0; nf < 8; nf++) {
            const int c = wn + cl + nf * 8;
            float v0 = acc[mf][nf][0] + sBias[c];
            float v1 = acc[mf][nf][1] + sBias[c + 1];
            float v2 = acc[mf][nf][2] + sBias[c];
            float v3 = acc[mf][nf][3] + sBias[c + 1];
            acc[mf][nf][0] = v0; acc[mf][nf][1] = v1;
            acc[mf][nf][2] = v2; acc[mf][nf][3] = v3;
            s0 += v0 + v1; q0 += v0 * v0 + v1 * v1;
            s1 += v2 + v3; q1 += v2 * v2 + v3 * v3;
        }
#pragma unroll
        for (int o = 1; o <= 2; o <<= 1) {
            s0 += __shfl_xor_sync(0xffffffffu, s0, o);
            q0 += __shfl_xor_sync(0xffffffffu, q0, o);
            s1 += __shfl_xor_sync(0xffffffffu, s1, o);
            q1 += __shfl_xor_sync(0xffffffffu, q1, o);
        }
        if ((lane & 3) == 0) {
            atomicAdd(&rsum[wm + mf * 16 + rl], s0);
            atomicAdd(&rsq [wm + mf * 16 + rl], q0);
            atomicAdd(&rsum[wm + mf * 16 + rl + 8], s1);
            atomicAdd(&rsq [wm + mf * 16 + rl + 8], q1);
        }
    }
    __syncthreads();
#pragma unroll
    for (int mf = 0; mf < 2; mf++) {
        const int r0 = wm + mf * 16 + rl, r1 = r0 + 8;
        const float m0 = rsum[r0] * (1.f / DD);
        const float i0 = rsqrtf(rsq[r0] * (1.f / DD) - m0 * m0 + EPS);
        const float m1 = rsum[r1] * (1.f / DD);
        const float i1 = rsqrtf(rsq[r1] * (1.f / DD) - m1 * m1 + EPS);
        __half* d0 = n1h + (size_t)(row0 + r0) * DD;
        __half* d1 = n1h + (size_t)(row0 + r1) * DD;
#pragma unroll
        for (int nf = 0; nf < 8; nf++) {
            const int c = wn + cl + nf * 8;
            __half2 h0 = __floats2half2_rn(
                (acc[mf][nf][0] - m0) * i0 * sG[c] + sBv[c],
                (acc[mf][nf][1] - m0) * i0 * sG[c + 1] + sBv[c + 1]);
            __half2 h1 = __floats2half2_rn(
                (acc[mf][nf][2] - m1) * i1 * sG[c] + sBv[c],
                (acc[mf][nf][3] - m1) * i1 * sG[c + 1] + sBv[c + 1]);
            *(__half2*)(d0 + c) = h0;
            *(__half2*)(d1 + c) = h1;
        }
    }
}

// ============ ctx via HMMA: 3 buffers, prefetch distance 2 ===================
__global__ __launch_bounds__(256) void ctx_mma_k(
    const __half* __restrict__ Eg, const __half* __restrict__ Yg,
    float* __restrict__ Spart)
{
    __shared__ __align__(16) __half sY[3][128 * 32];
    __shared__ __align__(16) __half sE[3][128 * 32];
    __shared__ float sS[32 * 32];

    const int kc = blockIdx.x, bh = blockIdx.y;
    const int b = bh >> 3, h = bh & 7;
    const int t = threadIdx.x, lane = t & 31, w = t >> 5;

    for (int i = t; i < 1024; i += 256) sS[i] = 0.f;

    const uint32_t uY = s2u(sY), uE = s2u(sE);
    const size_t gbase = (size_t)b * NN + kc * 1024;

    float acc[2][4][4];
#pragma unroll
    for (int m = 0; m < 2; m++)
#pragma unroll
        for (int n = 0; n < 4; n++)
#pragma unroll
            for (int k = 0; k < 4; k++) acc[m][n][k] = 0.f;

    auto stage = [&](int st, int sub) {
#pragma unroll
        for (int j = 0; j < 2; j++) {
            const int idx = t + j * 256;
            const int tok = idx >> 2, c4 = idx & 3;
            const size_t grow = gbase + sub * 128 + tok;
            cpa16(uY + st * 8192 + sw_off(tok, c4),
                  Yg + grow * DD + h * DK + c4 * 8);
            cpa16(uE + st * 8192 + sw_off(tok, c4),
                  Eg + grow * DD + h * DK + c4 * 8);
        }
        CP_COMMIT();
    };

    const int tb = w * 16;
    const int aTok = tb + (lane & 7) + ((lane >> 4) & 1) * 8;
    const int aChB = (lane >> 3) & 1;
    const int bTok = tb + (lane & 7) + ((lane >> 3) & 1) * 8;
    const int bChB = (lane >> 4) & 1;

    stage(0, 0);
    stage(1, 1);
    for (int sub = 0; sub < 8; sub++) {
        if (sub < 7) CP_WAIT1(); else CP_WAIT0();
        __syncthreads();
        if (sub + 2 < 8) stage((sub + 2) % 3, sub + 2);

        const int buf = sub % 3;
        const uint32_t uYb = uY + buf * 8192, uEb = uE + buf * 8192;
        uint32_t aY[2][4], bE[2][4];
#pragma unroll
        for (int m = 0; m < 2; m++)
            ldsm4t(aY[m], uYb + sw_off(aTok, m * 2 + aChB));
#pragma unroll
        for (int eh = 0; eh < 2; eh++)
            ldsm4t(bE[eh], uEb + sw_off(bTok, eh * 2 + bChB));
#pragma unroll
        for (int m = 0; m < 2; m++)
#pragma unroll
            for (int n = 0; n < 4; n++)
                mma16816(acc[m][n], aY[m], &bE[n >> 1][(n & 1) * 2]);
    }

    const int dg = lane >> 2, e0 = (lane & 3) * 2;
#pragma unroll
    for (int m = 0; m < 2; m++)
#pragma unroll
        for (int n = 0; n < 4; n++) {
            const int d = m * 16 + dg, e = n * 8 + e0;
            atomicAdd(&sS[d * 32 + e],           acc[m][n][0]);
            atomicAdd(&sS[d * 32 + e + 1],       acc[m][n][1]);
            atomicAdd(&sS[(d + 8) * 32 + e],     acc[m][n][2]);
            atomicAdd(&sS[(d + 8) * 32 + e + 1], acc[m][n][3]);
        }
    __syncthreads();

    float* op = Spart + ((size_t)(kc * 64) + bh) * (DK * DK);
#pragma unroll
    for (int i = 0; i < 4; i++)
        op[t + i * 256] = sS[t + i * 256];
}

// ---- W2eff fused with ctx_final: creg from Spart, ksum = local column sum ---
__global__ __launch_bounds__(256) void w2eff_k(
    const float* __restrict__ Spart, const float* __restrict__ rw,
    __half* __restrict__ b2h)
{
    __shared__ __align__(16) float rws[8 * 256];
    const int b  = blockIdx.x;
    const int o0 = blockIdx.y * 8;
    const int t  = threadIdx.x;
    const int h  = t >> 5, e = t & 31;

    const float4* rsrc = (const float4*)(rw + (size_t)o0 * DD);
    float4* rdst = (float4*)rws;
    rdst[t]       = rsrc[t];
    rdst[t + 256] = rsrc[t + 256];

    // creg[d] = sum of 4 Spart slices; ksum = sum over d of own column
    float creg[32];
    float ksum = 0.f;
    const float* sp = Spart + ((size_t)(b * 8 + h)) * 1024 + e;
#pragma unroll
    for (int d = 0; d < 32; d++) {
        float s = sp[d * 32] + sp[65536 + d * 32]
                + sp[131072 + d * 32] + sp[196608 + d * 32];
        creg[d] = s;
        ksum += s;
    }
    const float inv = 1.0f / ksum;
#pragma unroll
    for (int d = 0; d < 32; d++) creg[d] *= inv;
    __syncthreads();

#pragma unroll
    for (int j = 0; j < 8; j++) {
        const float* rb = rws + j * 256 + h * DK;
        float acc = 0.f;
#pragma unroll
        for (int d = 0; d < 32; d++) acc += creg[d] * rb[d];
        b2h[((size_t)b * D2 + o0 + j) * DD + t] = __float2half_rn(acc);
    }
}

// ---------------- W1 transpose + fp16 ----------------------------------------
__global__ void convert_w1_k(const float* __restrict__ W,
                             __half* __restrict__ wh)
{
    __shared__ float tile[32][33];
    const int n0 = blockIdx.x * 32;
    const int k0 = blockIdx.y * 32;
    const int x = threadIdx.x, y = threadIdx.y;
#pragma unroll
    for (int i = 0; i < 32; i += 8)
        tile[y + i][x] = W[(size_t)(k0 + y + i) * DD + n0 + x];
    __syncthreads();
#pragma unroll
    for (int i = 0; i < 32; i += 8)
        wh[(size_t)(n0 + y + i) * D2 + k0 + x] = __float2half_rn(tile[x][y + i]);
}

// ============ GEMM2 fused (proven R9 config: 3-stage, distance 2) ============
#define G2_SA_ST  4096
#define G2_SB_ST  32768
#define G2_SB     (3 * G2_SA_ST)
#define G2_VEC    (G2_SB + 3 * G2_SB_ST)
#define G2_RED    (G2_VEC + 3 * 512 * 4)
#define G2_SMEM   (G2_RED + 2 * 64 * 4)

__global__ __launch_bounds__(512, 1) void gemm2_ln_k(
    const __half* __restrict__ n1h, const __half* __restrict__ b2,
    const float* __restrict__ bias, const float* __restrict__ g,
    const float* __restrict__ bvec, const float* __restrict__ x1,
    float* __restrict__ outp)
{
    extern __shared__ char smem[];
    const uint32_t uA = s2u(smem);
    const uint32_t uB = uA + G2_SB;
    float* sBias = (float*)(smem + G2_VEC);
    float* sG    = sBias + 512;
    float* sBv   = sG + 512;
    float* rsum  = (float*)(smem + G2_RED);
    float* rsq   = rsum + 64;

    const int t = threadIdx.x, lane = t & 31, wid = t >> 5;
    const int wm = (wid & 1) * 32;
    const int wn = (wid >> 1) * 64;
    const int row0 = blockIdx.x * 64;
    const int b = blockIdx.x >> 6;
    const __half* Bp = b2 + (size_t)b * D2 * DD;

    sBias[t] = bias[t]; sG[t] = g[t]; sBv[t] = bvec[t];
    if (t < 64) { rsum[t] = 0.f; rsq[t] = 0.f; }

    const int ar = t >> 2, aq = t & 3;
    const __half* aptr = n1h + (size_t)(row0 + ar) * DD + aq * 8;
    const uint32_t staA = sw_off(ar, aq);

    float acc[2][8][4];
#pragma unroll
    for (int i = 0; i < 2; i++)
#pragma unroll
        for (int j = 0; j < 8; j++)
#pragma unroll
            for (int k = 0; k < 4; k++) acc[i][j][k] = 0.f;

    const int ti = lane >> 3, tr = lane & 7;
    const int a_dm = (ti & 1) * 8, a_dkc = ti >> 1;
    const int b_dn = (ti >> 1) * 8, b_dkc = ti & 1;

    auto stage = [&](int s, int kk) {
        const int k0 = kk * 32;
        if (t < 256) cpa16(uA + s * G2_SA_ST + staA, aptr + k0);
#pragma unroll
        for (int j = 0; j < 4; j++) {
            const int idx = t + j * 512;
            const int br = idx >> 2, bq = idx & 3;
            cpa16(uB + s * G2_SB_ST + sw_off(br, bq),
                  Bp + (size_t)br * DD + k0 + bq * 8);
        }
        CP_COMMIT();
    };

    stage(0, 0);
    stage(1, 1);

    const int nk = DD / 32;   // 8
    for (int kk = 0; kk < nk; kk++) {
        if (kk + 1 < nk) CP_WAIT1(); else CP_WAIT0();
        __syncthreads();
        if (kk + 2 < nk) stage((kk + 2) % 3, kk + 2);
        const int buf = kk % 3;
        const uint32_t bA = uA + buf * G2_SA_ST, bB = uB + buf * G2_SB_ST;
#pragma unroll
        for (int ks = 0; ks < 2; ks++) {
            uint32_t af[2][4], bf[4][4];
#pragma unroll
            for (int mf = 0; mf < 2; mf++)
                ldsm4(af[mf], bA + sw_off(wm + mf * 16 + a_dm + tr, ks * 2 + a_dkc));
#pragma unroll
            for (int g2 = 0; g2 < 4; g2++)
                ldsm4(bf[g2], bB + sw_off(wn + g2 * 16 + b_dn + tr, ks * 2 + b_dkc));
#pragma unroll
            for (int mf = 0; mf < 2; mf++)
#pragma unroll
                for (int nf = 0; nf < 8; nf++)
                    mma16816(acc[mf][nf], af[mf], &bf[nf >> 1][(nf & 1) * 2]);
        }
    }

    const int rl = lane >> 2, cl = (lane & 3) * 2;
#pragma unroll
    for (int mf = 0; mf < 2; mf++) {
        float s0 = 0.f, q0 = 0.f, s1 = 0.f, q1 = 0.f;
#pragma unroll
        for (int nf = 0; nf < 8; nf++) {
            const int c = wn + cl + nf * 8;
            float v0 = acc[mf][nf][0] + sBias[c];
            float v1 = acc[mf][nf][1] + sBias[c + 1];
            float v2 = acc[mf][nf][2] + sBias[c];
            float v3 = acc[mf][nf][3] + sBias[c + 1];
            acc[mf][nf][0] = v0; acc[mf][nf][1] = v1;
            acc[mf][nf][2] = v2; acc[mf][nf][3] = v3;
            s0 += v0 + v1; q0 += v0 * v0 + v1 * v1;
            s1 += v2 + v3; q1 += v2 * v2 + v3 * v3;
        }
#pragma unroll
        for (int o = 1; o <= 2; o <<= 1) {
            s0 += __shfl_xor_sync(0xffffffffu, s0, o);
            q0 += __shfl_xor_sync(0xffffffffu, q0, o);
            s1 += __shfl_xor_sync(0xffffffffu, s1, o);
            q1 += __shfl_xor_sync(0xffffffffu, q1, o);
        }
        if ((lane & 3) == 0) {
            atomicAdd(&rsum[wm + mf * 16 + rl], s0);
            atomicAdd(&rsq [wm + mf * 16 + rl], q0);
            atomicAdd(&rsum[wm + mf * 16 + rl + 8], s1);
            atomicAdd(&rsq [wm + mf * 16 + rl + 8], q1);
        }
    }
    __syncthreads();
#pragma unroll
    for (int mf = 0; mf < 2; mf++) {
        const int r0 = wm + mf * 16 + rl, r1 = r0 + 8;
        const float m0 = rsum[r0] * (1.f / D2);
        const float i0 = rsqrtf(rsq[r0] * (1.f / D2) - m0 * m0 + EPS);
        const float m1 = rsum[r1] * (1.f / D2);
        const float i1 = rsqrtf(rsq[r1] * (1.f / D2) - m1 * m1 + EPS);
        const float* x0 = x1 + (size_t)(row0 + r0) * D2;
        const float* x1p = x1 + (size_t)(row0 + r1) * D2;
        float* d0 = outp + (size_t)(row0 + r0) * D2;
        float* d1 = outp + (size_t)(row0 + r1) * D2;
#pragma unroll
        for (int nf = 0; nf < 8; nf++) {
            const int c = wn + cl + nf * 8;
            float2 xa = *(const float2*)(x0 + c);
            float2 xb = *(const float2*)(x1p + c);
            float2 o0, o1;
            o0.x = xa.x + (acc[mf][nf][0] - m0) * i0 * sG[c] + sBv[c];
            o0.y = xa.y + (acc[mf][nf][1] - m0) * i0 * sG[c + 1] + sBv[c + 1];
            o1.x = xb.x + (acc[mf][nf][2] - m1) * i1 * sG[c] + sBv[c];
            o1.y = xb.y + (acc[mf][nf][3] - m1) * i1 * sG[c + 1] + sBv[c + 1];
            *(float2*)(d0 + c) = o0;
            *(float2*)(d1 + c) = o1;
        }
    }
}

// ---------------- host launch: fork-join dual-stream (R13 schedule) ----------
extern "C" void kernel_launch(void* const* d_in, const int* in_sizes, int n_in,
                              void* d_out, int out_size)
{
    const float* x1        = (const float*)d_in[0];
    const float* x2        = (const float*)d_in[1];
    const float* linear_w  = (const float*)d_in[2];
    const float* linear_b  = (const float*)d_in[3];
    const float* ln1_g     = (const float*)d_in[4];
    const float* ln1_b     = (const float*)d_in[5];
    const float* reproj_w  = (const float*)d_in[6];
    const float* reproj_b  = (const float*)d_in[7];
    const float* ln_attn_g = (const float*)d_in[8];
    const float* ln_attn_b = (const float*)d_in[9];
    float* out = (float*)d_out;

    float *Spart;
    __half *x1h, *n1h, *w1h, *b2h, *Eg, *Yg;
    cudaGetSymbolAddress((void**)&x1h,  g_x1h);
    cudaGetSymbolAddress((void**)&n1h,  g_n1h);
    cudaGetSymbolAddress((void**)&Eg,   g_E);
    cudaGetSymbolAddress((void**)&Yg,   g_Y);
    cudaGetSymbolAddress((void**)&w1h,  g_w1h);
    cudaGetSymbolAddress((void**)&b2h,  g_b2h);
    cudaGetSymbolAddress((void**)&Spart,g_Spart);

    cudaFuncSetAttribute(gemm1_ln_k, cudaFuncAttributeMaxDynamicSharedMemorySize,
                         G1_SMEM);
    cudaFuncSetAttribute(gemm2_ln_k, cudaFuncAttributeMaxDynamicSharedMemorySize,
                         G2_SMEM);

    static cudaStream_t sB = nullptr;
    static cudaEvent_t evFork = nullptr, evJoin = nullptr;
    if (sB == nullptr) {
        cudaStreamCreateWithFlags(&sB, cudaStreamNonBlocking);
        cudaEventCreateWithFlags(&evFork, cudaEventDisableTiming);
        cudaEventCreateWithFlags(&evJoin, cudaEventDisableTiming);
    }

    // main: W1 prep (independent), then fork
    convert_w1_k<<<dim3(DD / 32, D2 / 32), dim3(32, 8)>>>(linear_w, w1h);
    cudaEventRecord(evFork, 0);
    cudaStreamWaitEvent(sB, evFork, 0);

    // side chain: x1->fp16 + LN(x2)/exp, ctx stats, W2eff (fused ctx_final)
    prep_k<<<RR / 16, 256, 0, sB>>>(x1, x2, ln1_g, ln1_b, x1h, Eg, Yg);
    ctx_mma_k<<<dim3(4, 64), 256, 0, sB>>>(Eg, Yg, Spart);
    // main: GEMM1 (profiled slot 4) — needs x1h, so side stream computes it;
    // gemm1 must wait for prep. Record a mid-chain event.
    static cudaEvent_t evPrep = nullptr;
    if (evPrep == nullptr)
        cudaEventCreateWithFlags(&evPrep, cudaEventDisableTiming);
    cudaEventRecord(evPrep, sB);          // after prep+ctx_mma submitted; prep done => x1h ready
    w2eff_k<<<dim3(Bb, D2 / 8), 256, 0, sB>>>(Spart, reproj_w, b2h);
    cudaEventRecord(evJoin, sB);

    // main: GEMM1 waits on x1h (prep, via evPrep which is ordered after ctx_mma too)
    cudaStreamWaitEvent(0, evPrep, 0);
    gemm1_ln_k<<<RR / 128, 512, G1_SMEM>>>(x1h, w1h, linear_b, ln1_g, ln1_b, n1h);

    // join: GEMM2 needs n1h (main) and b2h (side)
    cudaStreamWaitEvent(0, evJoin, 0);
    gemm2_ln_k<<<RR / 64, 512, G2_SMEM>>>(n1h, b2h, reproj_b, ln_attn_g,
                                          ln_attn_b, x1, out);
}

// round 17
// speedup vs baseline: 1.1265x; 1.1265x over previous
#include <cuda_runtime.h>
#include <cuda_fp16.h>
#include <cstdint>
#include <math.h>

#define Bb     8
#define NN     4096
#define RR     32768
#define DD     256
#define D2     512
#define HEADS  8
#define DK     32
#define EPS    1e-5f

// ---------------- scratch (device globals; no runtime allocation) -----------
__device__ __align__(16) __half g_n1h [RR * DD];
__device__ __align__(16) __half g_E   [RR * DD];
__device__ __align__(16) __half g_Y   [RR * DD];
__device__ __align__(16) __half g_w1h [DD * D2];
__device__ __align__(16) __half g_b2h [Bb * D2 * DD];
__device__ __align__(16) float  g_Spart[4 * Bb * HEADS * DK * DK];

// ---------------- helpers ----------------------------------------------------
__device__ __forceinline__ uint32_t s2u(const void* p) {
    uint32_t a;
    asm("{ .reg .u64 t; cvta.to.shared.u64 t, %1; cvt.u32.u64 %0, t; }"
        : "=r"(a) : "l"(p));
    return a;
}
__device__ __forceinline__ void cvt8(const float4& a, const float4& b, uint4& o) {
    __half2 h0 = __floats2half2_rn(a.x, a.y);
    __half2 h1 = __floats2half2_rn(a.z, a.w);
    __half2 h2 = __floats2half2_rn(b.x, b.y);
    __half2 h3 = __floats2half2_rn(b.z, b.w);
    o.x = *reinterpret_cast<uint32_t*>(&h0);
    o.y = *reinterpret_cast<uint32_t*>(&h1);
    o.z = *reinterpret_cast<uint32_t*>(&h2);
    o.w = *reinterpret_cast<uint32_t*>(&h3);
}
__device__ __forceinline__ void ldsm4(uint32_t* r, uint32_t addr) {
    asm volatile("ldmatrix.sync.aligned.m8n8.x4.shared.b16 {%0,%1,%2,%3}, [%4];"
                 : "=r"(r[0]), "=r"(r[1]), "=r"(r[2]), "=r"(r[3]) : "r"(addr));
}
__device__ __forceinline__ void ldsm4t(uint32_t* r, uint32_t addr) {
    asm volatile("ldmatrix.sync.aligned.m8n8.x4.trans.shared.b16 {%0,%1,%2,%3}, [%4];"
                 : "=r"(r[0]), "=r"(r[1]), "=r"(r[2]), "=r"(r[3]) : "r"(addr));
}
__device__ __forceinline__ void mma16816(float* c, const uint32_t* a,
                                         const uint32_t* b) {
    asm volatile(
        "mma.sync.aligned.m16n8k16.row.col.f32.f16.f16.f32 "
        "{%0,%1,%2,%3}, {%4,%5,%6,%7}, {%8,%9}, {%0,%1,%2,%3};"
        : "+f"(c[0]), "+f"(c[1]), "+f"(c[2]), "+f"(c[3])
        : "r"(a[0]), "r"(a[1]), "r"(a[2]), "r"(a[3]), "r"(b[0]), "r"(b[1]));
}
__device__ __forceinline__ void cpa16(uint32_t dst, const void* src) {
    asm volatile("cp.async.ca.shared.global [%0], [%1], 16;" :: "r"(dst), "l"(src));
}
#define CP_COMMIT() asm volatile("cp.async.commit_group;")
#define CP_WAIT0()  asm volatile("cp.async.wait_group 0;")
#define CP_WAIT1()  asm volatile("cp.async.wait_group 1;")

__device__ __forceinline__ uint32_t sw_off(int row, int cch) {
    return (uint32_t)(row * 64 + ((cch ^ ((row >> 1) & 3)) << 4));
}

// ============ prep: LN(x2)+exp+softmax -> E,Y (2 rows per warp) ==============
__global__ __launch_bounds__(256) void prep_k(
    const float* __restrict__ x2, const float* __restrict__ g,
    const float* __restrict__ b, __half* __restrict__ Eg,
    __half* __restrict__ Yg)
{
    const int w    = threadIdx.x >> 5;
    const int lane = threadIdx.x & 31;
    const int r0   = blockIdx.x * 16 + w * 2;
    const int ci   = lane * 8;

    float4 A[2], C[2];
#pragma unroll
    for (int rr = 0; rr < 2; rr++) {
        const float* p = x2 + (size_t)(r0 + rr) * DD + ci;
        A[rr] = *(const float4*)p;
        C[rr] = *(const float4*)(p + 4);
    }

    float4 g0 = *(const float4*)(g + ci);
    float4 g1 = *(const float4*)(g + ci + 4);
    float4 b0 = *(const float4*)(b + ci);
    float4 b1 = *(const float4*)(b + ci + 4);

    float sm[2], rs[2];
#pragma unroll
    for (int rr = 0; rr < 2; rr++) {
        float s = A[rr].x + A[rr].y + A[rr].z + A[rr].w
                + C[rr].x + C[rr].y + C[rr].z + C[rr].w;
#pragma unroll
        for (int o = 16; o; o >>= 1) s += __shfl_xor_sync(0xffffffffu, s, o);
        sm[rr] = s * (1.0f / DD);
    }
#pragma unroll
    for (int rr = 0; rr < 2; rr++) {
        A[rr].x -= sm[rr]; A[rr].y -= sm[rr]; A[rr].z -= sm[rr]; A[rr].w -= sm[rr];
        C[rr].x -= sm[rr]; C[rr].y -= sm[rr]; C[rr].z -= sm[rr]; C[rr].w -= sm[rr];
        float s2 = A[rr].x*A[rr].x + A[rr].y*A[rr].y + A[rr].z*A[rr].z + A[rr].w*A[rr].w
                 + C[rr].x*C[rr].x + C[rr].y*C[rr].y + C[rr].z*C[rr].z + C[rr].w*C[rr].w;
#pragma unroll
        for (int o = 16; o; o >>= 1) s2 += __shfl_xor_sync(0xffffffffu, s2, o);
        rs[rr] = rsqrtf(s2 * (1.0f / DD) + EPS);
    }

#pragma unroll
    for (int rr = 0; rr < 2; rr++) {
        float4 e0, e1;
        e0.x = __expf(A[rr].x*rs[rr]*g0.x + b0.x);
        e0.y = __expf(A[rr].y*rs[rr]*g0.y + b0.y);
        e0.z = __expf(A[rr].z*rs[rr]*g0.z + b0.z);
        e0.w = __expf(A[rr].w*rs[rr]*g0.w + b0.w);
        e1.x = __expf(C[rr].x*rs[rr]*g1.x + b1.x);
        e1.y = __expf(C[rr].y*rs[rr]*g1.y + b1.y);
        e1.z = __expf(C[rr].z*rs[rr]*g1.z + b1.z);
        e1.w = __expf(C[rr].w*rs[rr]*g1.w + b1.w);

        float qs = e0.x + e0.y + e0.z + e0.w + e1.x + e1.y + e1.z + e1.w;
        qs += __shfl_xor_sync(0xffffffffu, qs, 1);
        qs += __shfl_xor_sync(0xffffffffu, qs, 2);
        const float inv = 1.0f / qs;

        float4 y0, y1;
        y0.x = e0.x * inv; y0.y = e0.y * inv; y0.z = e0.z * inv; y0.w = e0.w * inv;
        y1.x = e1.x * inv; y1.y = e1.y * inv; y1.z = e1.z * inv; y1.w = e1.w * inv;

        uint4 ev, yv;
        cvt8(e0, e1, ev);
        cvt8(y0, y1, yv);
        *(uint4*)(Eg + (size_t)(r0 + rr) * DD + ci) = ev;
        *(uint4*)(Yg + (size_t)(r0 + rr) * DD + ci) = yv;
    }
}

// ============ GEMM1 fused: n1h = fp16( LN(x1 @ W1 + b1) ) ====================
// fp32 A staged via cp.async, converted thread-locally (R12/R13 proven version).
#define G1_A32_ST 16384
#define G1_AH_ST  8192
#define G1_B_ST   16384
#define G1_AH_OFF (3 * G1_A32_ST)
#define G1_B_OFF  (G1_AH_OFF + 3 * G1_AH_ST)
#define G1_VEC    (G1_B_OFF + 3 * G1_B_ST)
#define G1_RED    (G1_VEC + 3 * 256 * 4)
#define G1_SMEM   (G1_RED + 2 * 128 * 4)

__global__ __launch_bounds__(512, 1) void gemm1_ln_k(
    const float* __restrict__ x1, const __half* __restrict__ w1,
    const float* __restrict__ bias, const float* __restrict__ g,
    const float* __restrict__ bvec, __half* __restrict__ n1h)
{
    extern __shared__ char smem[];
    const uint32_t uA32 = s2u(smem);
    const uint32_t uAh  = uA32 + G1_AH_OFF;
    const uint32_t uB   = uA32 + G1_B_OFF;
    float* sBias = (float*)(smem + G1_VEC);
    float* sG    = sBias + 256;
    float* sBv   = sG + 256;
    float* rsum  = (float*)(smem + G1_RED);
    float* rsq   = rsum + 128;

    const int t = threadIdx.x, lane = t & 31, wid = t >> 5;
    const int wm = (wid & 3) * 32;
    const int wn = (wid >> 2) * 64;
    const int row0 = blockIdx.x * 128;

    if (t < 256) { sBias[t] = bias[t]; sG[t] = g[t]; sBv[t] = bvec[t]; }
    if (t < 128) { rsum[t] = 0.f; rsq[t] = 0.f; }

    const int ar = t >> 2, aq = t & 3;
    const float* aptr = x1 + (size_t)(row0 + ar) * D2 + aq * 8;
    const uint32_t a32off = (uint32_t)(ar * 128 + aq * 32);
    const uint32_t staA   = sw_off(ar, aq);

    float acc[2][8][4];
#pragma unroll
    for (int i = 0; i < 2; i++)
#pragma unroll
        for (int j = 0; j < 8; j++)
#pragma unroll
            for (int k = 0; k < 4; k++) acc[i][j][k] = 0.f;

    const int ti = lane >> 3, tr = lane & 7;
    const int a_dm = (ti & 1) * 8, a_dkc = ti >> 1;
    const int b_dn = (ti >> 1) * 8, b_dkc = ti & 1;

    auto stage = [&](int s, int kk) {
        const int k0 = kk * 32;
        cpa16(uA32 + s * G1_A32_ST + a32off, aptr + k0);
        cpa16(uA32 + s * G1_A32_ST + a32off + 16, aptr + k0 + 4);
#pragma unroll
        for (int j = 0; j < 2; j++) {
            const int idx = t + j * 512;
            const int br = idx >> 2, bq = idx & 3;
            cpa16(uB + s * G1_B_ST + sw_off(br, bq),
                  w1 + (size_t)br * D2 + k0 + bq * 8);
        }
        CP_COMMIT();
    };

    stage(0, 0);
    stage(1, 1);

    const int nk = D2 / 32;   // 16
    for (int kk = 0; kk < nk; kk++) {
        if (kk + 1 < nk) CP_WAIT1(); else CP_WAIT0();
        const int buf = kk % 3;
        {   // convert own staged fp32 A chunk -> swizzled fp16 (thread-local)
            const char* sp = smem + buf * G1_A32_ST + a32off;
            float4 f0 = *(const float4*)sp;
            float4 f1 = *(const float4*)(sp + 16);
            uint4 v; cvt8(f0, f1, v);
            *(uint4*)(smem + G1_AH_OFF + buf * G1_AH_ST + staA) = v;
        }
        __syncthreads();
        if (kk + 2 < nk) stage((kk + 2) % 3, kk + 2);
        const uint32_t bA = uAh + buf * G1_AH_ST, bB = uB + buf * G1_B_ST;
#pragma unroll
        for (int ks = 0; ks < 2; ks++) {
            uint32_t af[2][4], bf[4][4];
#pragma unroll
            for (int mf = 0; mf < 2; mf++)
                ldsm4(af[mf], bA + sw_off(wm + mf * 16 + a_dm + tr, ks * 2 + a_dkc));
#pragma unroll
            for (int g2 = 0; g2 < 4; g2++)
                ldsm4(bf[g2], bB + sw_off(wn + g2 * 16 + b_dn + tr, ks * 2 + b_dkc));
#pragma unroll
            for (int mf = 0; mf < 2; mf++)
#pragma unroll
                for (int nf = 0; nf < 8; nf++)
                    mma16816(acc[mf][nf], af[mf], &bf[nf >> 1][(nf & 1) * 2]);
        }
    }

    // ---- epilogue: bias + LN over 256 cols, write fp16 ----
    const int rl = lane >> 2, cl = (lane & 3) * 2;
#pragma unroll
    for (int mf = 0; mf < 2; mf++) {
        float s0 = 0.f, q0 = 0.f, s1 = 0.f, q1 = 0.f;
#pragma unroll
        for (int nf = 0; nf < 8; nf++) {
            const int c = wn + cl + nf * 8;
            float v0 = acc[mf][nf][0] + sBias[c];
            float v1 = acc[mf][nf][1] + sBias[c + 1];
            float v2 = acc[mf][nf][2] + sBias[c];
            float v3 = acc[mf][nf][3] + sBias[c + 1];
            acc[mf][nf][0] = v0; acc[mf][nf][1] = v1;
            acc[mf][nf][2] = v2; acc[mf][nf][3] = v3;
            s0 += v0 + v1; q0 += v0 * v0 + v1 * v1;
            s1 += v2 + v3; q1 += v2 * v2 + v3 * v3;
        }
#pragma unroll
        for (int o = 1; o <= 2; o <<= 1) {
            s0 += __shfl_xor_sync(0xffffffffu, s0, o);
            q0 += __shfl_xor_sync(0xffffffffu, q0, o);
            s1 += __shfl_xor_sync(0xffffffffu, s1, o);
            q1 += __shfl_xor_sync(0xffffffffu, q1, o);
        }
        if ((lane & 3) == 0) {
            atomicAdd(&rsum[wm + mf * 16 + rl], s0);
            atomicAdd(&rsq [wm + mf * 16 + rl], q0);
            atomicAdd(&rsum[wm + mf * 16 + rl + 8], s1);
            atomicAdd(&rsq [wm + mf * 16 + rl + 8], q1);
        }
    }
    __syncthreads();
#pragma unroll
    for (int mf = 0; mf < 2; mf++) {
        const int r0 = wm + mf * 16 + rl, r1 = r0 + 8;
        const float m0 = rsum[r0] * (1.f / DD);
        const float i0 = rsqrtf(rsq[r0] * (1.f / DD) - m0 * m0 + EPS);
        const float m1 = rsum[r1] * (1.f / DD);
        const float i1 = rsqrtf(rsq[r1] * (1.f / DD) - m1 * m1 + EPS);
        __half* d0 = n1h + (size_t)(row0 + r0) * DD;
        __half* d1 = n1h + (size_t)(row0 + r1) * DD;
#pragma unroll
        for (int nf = 0; nf < 8; nf++) {
            const int c = wn + cl + nf * 8;
            __half2 h0 = __floats2half2_rn(
                (acc[mf][nf][0] - m0) * i0 * sG[c] + sBv[c],
                (acc[mf][nf][1] - m0) * i0 * sG[c + 1] + sBv[c + 1]);
            __half2 h1 = __floats2half2_rn(
                (acc[mf][nf][2] - m1) * i1 * sG[c] + sBv[c],
                (acc[mf][nf][3] - m1) * i1 * sG[c + 1] + sBv[c + 1]);
            *(__half2*)(d0 + c) = h0;
            *(__half2*)(d1 + c) = h1;
        }
    }
}

// ============ ctx via HMMA: 3 buffers, prefetch distance 2 ===================
__global__ __launch_bounds__(256) void ctx_mma_k(
    const __half* __restrict__ Eg, const __half* __restrict__ Yg,
    float* __restrict__ Spart)
{
    __shared__ __align__(16) __half sY[3][128 * 32];
    __shared__ __align__(16) __half sE[3][128 * 32];
    __shared__ float sS[32 * 32];

    const int kc = blockIdx.x, bh = blockIdx.y;
    const int b = bh >> 3, h = bh & 7;
    const int t = threadIdx.x, lane = t & 31, w = t >> 5;

    for (int i = t; i < 1024; i += 256) sS[i] = 0.f;

    const uint32_t uY = s2u(sY), uE = s2u(sE);
    const size_t gbase = (size_t)b * NN + kc * 1024;

    float acc[2][4][4];
#pragma unroll
    for (int m = 0; m < 2; m++)
#pragma unroll
        for (int n = 0; n < 4; n++)
#pragma unroll
            for (int k = 0; k < 4; k++) acc[m][n][k] = 0.f;

    auto stage = [&](int st, int sub) {
#pragma unroll
        for (int j = 0; j < 2; j++) {
            const int idx = t + j * 256;
            const int tok = idx >> 2, c4 = idx & 3;
            const size_t grow = gbase + sub * 128 + tok;
            cpa16(uY + st * 8192 + sw_off(tok, c4),
                  Yg + grow * DD + h * DK + c4 * 8);
            cpa16(uE + st * 8192 + sw_off(tok, c4),
                  Eg + grow * DD + h * DK + c4 * 8);
        }
        CP_COMMIT();
    };

    const int tb = w * 16;
    const int aTok = tb + (lane & 7) + ((lane >> 4) & 1) * 8;
    const int aChB = (lane >> 3) & 1;
    const int bTok = tb + (lane & 7) + ((lane >> 3) & 1) * 8;
    const int bChB = (lane >> 4) & 1;

    stage(0, 0);
    stage(1, 1);
    for (int sub = 0; sub < 8; sub++) {
        if (sub < 7) CP_WAIT1(); else CP_WAIT0();
        __syncthreads();
        if (sub + 2 < 8) stage((sub + 2) % 3, sub + 2);

        const int buf = sub % 3;
        const uint32_t uYb = uY + buf * 8192, uEb = uE + buf * 8192;
        uint32_t aY[2][4], bE[2][4];
#pragma unroll
        for (int m = 0; m < 2; m++)
            ldsm4t(aY[m], uYb + sw_off(aTok, m * 2 + aChB));
#pragma unroll
        for (int eh = 0; eh < 2; eh++)
            ldsm4t(bE[eh], uEb + sw_off(bTok, eh * 2 + bChB));
#pragma unroll
        for (int m = 0; m < 2; m++)
#pragma unroll
            for (int n = 0; n < 4; n++)
                mma16816(acc[m][n], aY[m], &bE[n >> 1][(n & 1) * 2]);
    }

    const int dg = lane >> 2, e0 = (lane & 3) * 2;
#pragma unroll
    for (int m = 0; m < 2; m++)
#pragma unroll
        for (int n = 0; n < 4; n++) {
            const int d = m * 16 + dg, e = n * 8 + e0;
            atomicAdd(&sS[d * 32 + e],           acc[m][n][0]);
            atomicAdd(&sS[d * 32 + e + 1],       acc[m][n][1]);
            atomicAdd(&sS[(d + 8) * 32 + e],     acc[m][n][2]);
            atomicAdd(&sS[(d + 8) * 32 + e + 1], acc[m][n][3]);
        }
    __syncthreads();

    float* op = Spart + ((size_t)(kc * 64) + bh) * (DK * DK);
#pragma unroll
    for (int i = 0; i < 4; i++)
        op[t + i * 256] = sS[t + i * 256];
}

// ---- W2eff fused with ctx_final: creg from Spart, ksum = local column sum ---
__global__ __launch_bounds__(256) void w2eff_k(
    const float* __restrict__ Spart, const float* __restrict__ rw,
    __half* __restrict__ b2h)
{
    __shared__ __align__(16) float rws[8 * 256];
    const int b  = blockIdx.x;
    const int o0 = blockIdx.y * 8;
    const int t  = threadIdx.x;
    const int h  = t >> 5, e = t & 31;

    const float4* rsrc = (const float4*)(rw + (size_t)o0 * DD);
    float4* rdst = (float4*)rws;
    rdst[t]       = rsrc[t];
    rdst[t + 256] = rsrc[t + 256];

    float creg[32];
    float ksum = 0.f;
    const float* sp = Spart + ((size_t)(b * 8 + h)) * 1024 + e;
#pragma unroll
    for (int d = 0; d < 32; d++) {
        float s = sp[d * 32] + sp[65536 + d * 32]
                + sp[131072 + d * 32] + sp[196608 + d * 32];
        creg[d] = s;
        ksum += s;
    }
    const float inv = 1.0f / ksum;
#pragma unroll
    for (int d = 0; d < 32; d++) creg[d] *= inv;
    __syncthreads();

#pragma unroll
    for (int j = 0; j < 8; j++) {
        const float* rb = rws + j * 256 + h * DK;
        float acc = 0.f;
#pragma unroll
        for (int d = 0; d < 32; d++) acc += creg[d] * rb[d];
        b2h[((size_t)b * D2 + o0 + j) * DD + t] = __float2half_rn(acc);
    }
}

// ---------------- W1 transpose + fp16 ----------------------------------------
__global__ void convert_w1_k(const float* __restrict__ W,
                             __half* __restrict__ wh)
{
    __shared__ float tile[32][33];
    const int n0 = blockIdx.x * 32;
    const int k0 = blockIdx.y * 32;
    const int x = threadIdx.x, y = threadIdx.y;
#pragma unroll
    for (int i = 0; i < 32; i += 8)
        tile[y + i][x] = W[(size_t)(k0 + y + i) * DD + n0 + x];
    __syncthreads();
#pragma unroll
    for (int i = 0; i < 32; i += 8)
        wh[(size_t)(n0 + y + i) * D2 + k0 + x] = __float2half_rn(tile[x][y + i]);
}

// ============ GEMM2 fused (proven R9 config: 3-stage, distance 2) ============
#define G2_SA_ST  4096
#define G2_SB_ST  32768
#define G2_SB     (3 * G2_SA_ST)
#define G2_VEC    (G2_SB + 3 * G2_SB_ST)
#define G2_RED    (G2_VEC + 3 * 512 * 4)
#define G2_SMEM   (G2_RED + 2 * 64 * 4)

__global__ __launch_bounds__(512, 1) void gemm2_ln_k(
    const __half* __restrict__ n1h, const __half* __restrict__ b2,
    const float* __restrict__ bias, const float* __restrict__ g,
    const float* __restrict__ bvec, const float* __restrict__ x1,
    float* __restrict__ outp)
{
    extern __shared__ char smem[];
    const uint32_t uA = s2u(smem);
    const uint32_t uB = uA + G2_SB;
    float* sBias = (float*)(smem + G2_VEC);
    float* sG    = sBias + 512;
    float* sBv   = sG + 512;
    float* rsum  = (float*)(smem + G2_RED);
    float* rsq   = rsum + 64;

    const int t = threadIdx.x, lane = t & 31, wid = t >> 5;
    const int wm = (wid & 1) * 32;
    const int wn = (wid >> 1) * 64;
    const int row0 = blockIdx.x * 64;
    const int b = blockIdx.x >> 6;
    const __half* Bp = b2 + (size_t)b * D2 * DD;

    sBias[t] = bias[t]; sG[t] = g[t]; sBv[t] = bvec[t];
    if (t < 64) { rsum[t] = 0.f; rsq[t] = 0.f; }

    const int ar = t >> 2, aq = t & 3;
    const __half* aptr = n1h + (size_t)(row0 + ar) * DD + aq * 8;
    const uint32_t staA = sw_off(ar, aq);

    float acc[2][8][4];
#pragma unroll
    for (int i = 0; i < 2; i++)
#pragma unroll
        for (int j = 0; j < 8; j++)
#pragma unroll
            for (int k = 0; k < 4; k++) acc[i][j][k] = 0.f;

    const int ti = lane >> 3, tr = lane & 7;
    const int a_dm = (ti & 1) * 8, a_dkc = ti >> 1;
    const int b_dn = (ti >> 1) * 8, b_dkc = ti & 1;

    auto stage = [&](int s, int kk) {
        const int k0 = kk * 32;
        if (t < 256) cpa16(uA + s * G2_SA_ST + staA, aptr + k0);
#pragma unroll
        for (int j = 0; j < 4; j++) {
            const int idx = t + j * 512;
            const int br = idx >> 2, bq = idx & 3;
            cpa16(uB + s * G2_SB_ST + sw_off(br, bq),
                  Bp + (size_t)br * DD + k0 + bq * 8);
        }
        CP_COMMIT();
    };

    stage(0, 0);
    stage(1, 1);

    const int nk = DD / 32;   // 8
    for (int kk = 0; kk < nk; kk++) {
        if (kk + 1 < nk) CP_WAIT1(); else CP_WAIT0();
        __syncthreads();
        if (kk + 2 < nk) stage((kk + 2) % 3, kk + 2);
        const int buf = kk % 3;
        const uint32_t bA = uA + buf * G2_SA_ST, bB = uB + buf * G2_SB_ST;
#pragma unroll
        for (int ks = 0; ks < 2; ks++) {
            uint32_t af[2][4], bf[4][4];
#pragma unroll
            for (int mf = 0; mf < 2; mf++)
                ldsm4(af[mf], bA + sw_off(wm + mf * 16 + a_dm + tr, ks * 2 + a_dkc));
#pragma unroll
            for (int g2 = 0; g2 < 4; g2++)
                ldsm4(bf[g2], bB + sw_off(wn + g2 * 16 + b_dn + tr, ks * 2 + b_dkc));
#pragma unroll
            for (int mf = 0; mf < 2; mf++)
#pragma unroll
                for (int nf = 0; nf < 8; nf++)
                    mma16816(acc[mf][nf], af[mf], &bf[nf >> 1][(nf & 1) * 2]);
        }
    }

    const int rl = lane >> 2, cl = (lane & 3) * 2;
#pragma unroll
    for (int mf = 0; mf < 2; mf++) {
        float s0 = 0.f, q0 = 0.f, s1 = 0.f, q1 = 0.f;
#pragma unroll
        for (int nf = 0; nf < 8; nf++) {
            const int c = wn + cl + nf * 8;
            float v0 = acc[mf][nf][0] + sBias[c];
            float v1 = acc[mf][nf][1] + sBias[c + 1];
            float v2 = acc[mf][nf][2] + sBias[c];
            float v3 = acc[mf][nf][3] + sBias[c + 1];
            acc[mf][nf][0] = v0; acc[mf][nf][1] = v1;
            acc[mf][nf][2] = v2; acc[mf][nf][3] = v3;
            s0 += v0 + v1; q0 += v0 * v0 + v1 * v1;
            s1 += v2 + v3; q1 += v2 * v2 + v3 * v3;
        }
#pragma unroll
        for (int o = 1; o <= 2; o <<= 1) {
            s0 += __shfl_xor_sync(0xffffffffu, s0, o);
            q0 += __shfl_xor_sync(0xffffffffu, q0, o);
            s1 += __shfl_xor_sync(0xffffffffu, s1, o);
            q1 += __shfl_xor_sync(0xffffffffu, q1, o);
        }
        if ((lane & 3) == 0) {
            atomicAdd(&rsum[wm + mf * 16 + rl], s0);
            atomicAdd(&rsq [wm + mf * 16 + rl], q0);
            atomicAdd(&rsum[wm + mf * 16 + rl + 8], s1);
            atomicAdd(&rsq [wm + mf * 16 + rl + 8], q1);
        }
    }
    __syncthreads();
#pragma unroll
    for (int mf = 0; mf < 2; mf++) {
        const int r0 = wm + mf * 16 + rl, r1 = r0 + 8;
        const float m0 = rsum[r0] * (1.f / D2);
        const float i0 = rsqrtf(rsq[r0] * (1.f / D2) - m0 * m0 + EPS);
        const float m1 = rsum[r1] * (1.f / D2);
        const float i1 = rsqrtf(rsq[r1] * (1.f / D2) - m1 * m1 + EPS);
        const float* x0 = x1 + (size_t)(row0 + r0) * D2;
        const float* x1p = x1 + (size_t)(row0 + r1) * D2;
        float* d0 = outp + (size_t)(row0 + r0) * D2;
        float* d1 = outp + (size_t)(row0 + r1) * D2;
#pragma unroll
        for (int nf = 0; nf < 8; nf++) {
            const int c = wn + cl + nf * 8;
            float2 xa = *(const float2*)(x0 + c);
            float2 xb = *(const float2*)(x1p + c);
            float2 o0, o1;
            o0.x = xa.x + (acc[mf][nf][0] - m0) * i0 * sG[c] + sBv[c];
            o0.y = xa.y + (acc[mf][nf][1] - m0) * i0 * sG[c + 1] + sBv[c + 1];
            o1.x = xb.x + (acc[mf][nf][2] - m1) * i1 * sG[c] + sBv[c];
            o1.y = xb.y + (acc[mf][nf][3] - m1) * i1 * sG[c + 1] + sBv[c + 1];
            *(float2*)(d0 + c) = o0;
            *(float2*)(d1 + c) = o1;
        }
    }
}

// ---------------- host launch: fork-join dual-stream (R13 schedule) ----------
extern "C" void kernel_launch(void* const* d_in, const int* in_sizes, int n_in,
                              void* d_out, int out_size)
{
    const float* x1        = (const float*)d_in[0];
    const float* x2        = (const float*)d_in[1];
    const float* linear_w  = (const float*)d_in[2];
    const float* linear_b  = (const float*)d_in[3];
    const float* ln1_g     = (const float*)d_in[4];
    const float* ln1_b     = (const float*)d_in[5];
    const float* reproj_w  = (const float*)d_in[6];
    const float* reproj_b  = (const float*)d_in[7];
    const float* ln_attn_g = (const float*)d_in[8];
    const float* ln_attn_b = (const float*)d_in[9];
    float* out = (float*)d_out;

    float *Spart;
    __half *n1h, *w1h, *b2h, *Eg, *Yg;
    cudaGetSymbolAddress((void**)&n1h,  g_n1h);
    cudaGetSymbolAddress((void**)&Eg,   g_E);
    cudaGetSymbolAddress((void**)&Yg,   g_Y);
    cudaGetSymbolAddress((void**)&w1h,  g_w1h);
    cudaGetSymbolAddress((void**)&b2h,  g_b2h);
    cudaGetSymbolAddress((void**)&Spart,g_Spart);

    cudaFuncSetAttribute(gemm1_ln_k, cudaFuncAttributeMaxDynamicSharedMemorySize,
                         G1_SMEM);
    cudaFuncSetAttribute(gemm2_ln_k, cudaFuncAttributeMaxDynamicSharedMemorySize,
                         G2_SMEM);

    static cudaStream_t sB = nullptr;
    static cudaEvent_t evFork = nullptr, evJoin = nullptr;
    if (sB == nullptr) {
        cudaStreamCreateWithFlags(&sB, cudaStreamNonBlocking);
        cudaEventCreateWithFlags(&evFork, cudaEventDisableTiming);
        cudaEventCreateWithFlags(&evJoin, cudaEventDisableTiming);
    }

    // fork: side stream ordered after anything already on the main stream
    cudaEventRecord(evFork, 0);
    cudaStreamWaitEvent(sB, evFork, 0);

    // chain A (side stream): attention statistics -> W2eff (ctx_final fused)
    prep_k<<<RR / 16, 256, 0, sB>>>(x2, ln1_g, ln1_b, Eg, Yg);
    ctx_mma_k<<<dim3(4, 64), 256, 0, sB>>>(Eg, Yg, Spart);
    w2eff_k<<<dim3(Bb, D2 / 8), 256, 0, sB>>>(Spart, reproj_w, b2h);
    cudaEventRecord(evJoin, sB);

    // chain B (main stream): W1 prep -> GEMM1 (fp32 A, no producer dependency)
    convert_w1_k<<<dim3(DD / 32, D2 / 32), dim3(32, 8)>>>(linear_w, w1h);
    gemm1_ln_k<<<RR / 128, 512, G1_SMEM>>>(x1, w1h, linear_b, ln1_g, ln1_b, n1h);

    // join: GEMM2 needs n1h (main) and b2h (side)
    cudaStreamWaitEvent(0, evJoin, 0);
    gemm2_ln_k<<<RR / 64, 512, G2_SMEM>>>(n1h, b2h, reproj_b, ln_attn_g,
                                          ln_attn_b, x1, out);
}